// round 2
// baseline (speedup 1.0000x reference)
#include <cuda_runtime.h>

#define HID 16
#define NB 24

// subnet tile
#define TX 32
#define TY 16
#define HTX (TX + 2)   // 34
#define HTY (TY + 2)   // 18
#define ITX (TX + 4)   // 36
#define ITY (TY + 4)   // 20

// scratch (device globals: allocation-guard safe)
__device__ float g_L[NB * 256 * 512];
__device__ float g_H[NB * 256 * 512];
__device__ float g_A0[NB * 256 * 256];  // LL
__device__ float g_A1[NB * 256 * 256];  // HL
__device__ float g_A2[NB * 256 * 256];  // LH
__device__ float g_A3[NB * 256 * 256];  // HH

// ---------------------------------------------------------------------------
// K1: RGB->YUV + even/odd row split.
// x: (8,3,512,512). L/H: (24,256,512) with n = c*8 + b.
// ---------------------------------------------------------------------------
__global__ void rgb2yuv_split_kernel(const float* __restrict__ x) {
    int gx  = blockIdx.x * blockDim.x + threadIdx.x;  // 0..511
    int row = blockIdx.y;                             // 0..511
    int b   = blockIdx.z;                             // 0..7
    const size_t plane = 512 * 512;
    const float* xb = x + (size_t)b * 3 * plane + (size_t)row * 512 + gx;
    float r  = xb[0];
    float g  = xb[plane];
    float bl = xb[2 * plane];
    float Y =  0.299f * r + 0.587f * g + 0.114f * bl;
    float U = -0.147f * r - 0.289f * g + 0.436f * bl;
    float V =  0.615f * r - 0.515f * g - 0.100f * bl;
    float* dst = (row & 1) ? g_H : g_L;
    int i = row >> 1;
    const size_t p2 = 256 * 512;
    size_t off = (size_t)i * 512 + gx;
    dst[(size_t)(0 * 8 + b) * p2 + off] = Y;
    dst[(size_t)(1 * 8 + b) * p2 + off] = U;
    dst[(size_t)(2 * 8 + b) * p2 + off] = V;
}

// ---------------------------------------------------------------------------
// K2: fused subnet:  T += sign * conv2( relu( conv1(I) ) ), SAME padding.
// I,T: (24,h,w). W1: (16,1,3,3), W2: (1,16,3,3).
// One 32x16 output tile per CTA; hidden (16ch) staged in smem.
// IMPORTANT: the hidden feature map only exists inside the image; conv2's
// SAME padding pads it with ZEROS. So hidden values at global positions
// outside [0,h)x[0,w) must be 0, not relu(conv1(padded input)).
// ---------------------------------------------------------------------------
__global__ void __launch_bounds__(TX * TY) subnet_kernel(
    const float* __restrict__ I, float* __restrict__ T,
    const float* __restrict__ W1, const float* __restrict__ b1,
    const float* __restrict__ W2, const float* __restrict__ b2,
    float sign, int h, int w)
{
    __shared__ float sW1[HID * 9];
    __shared__ float sW2[HID * 9];
    __shared__ float sb1[HID];
    __shared__ float sb2;
    __shared__ float sIn[ITY][ITX];
    __shared__ float sHid[HID][HTY][HTX];

    const int tid = threadIdx.y * TX + threadIdx.x;
    const int n  = blockIdx.z;
    const int x0 = blockIdx.x * TX;
    const int y0 = blockIdx.y * TY;
    const float* In = I + (size_t)n * h * w;

    if (tid < HID * 9) { sW1[tid] = W1[tid]; sW2[tid] = W2[tid]; }
    if (tid < HID)     sb1[tid] = b1[tid];
    if (tid == 0)      sb2 = b2[0];

    // input tile with halo 2 (zero pad outside image)
    for (int idx = tid; idx < ITX * ITY; idx += TX * TY) {
        int iy = idx / ITX, ix = idx - iy * ITX;
        int gy = y0 + iy - 2, gx = x0 + ix - 2;
        float v = 0.f;
        if (gy >= 0 && gy < h && gx >= 0 && gx < w) v = In[(size_t)gy * w + gx];
        sIn[iy][ix] = v;
    }
    __syncthreads();

    // conv1 (1->16) + relu into sHid over the haloed hidden tile.
    // Hidden pixels outside the image are ZERO (conv2 SAME-padding semantics).
    for (int idx = tid; idx < HTX * HTY; idx += TX * TY) {
        int hy = idx / HTX, hx = idx - hy * HTX;
        int gy = y0 + hy - 1, gx = x0 + hx - 1;
        bool inside = (gy >= 0) && (gy < h) && (gx >= 0) && (gx < w);
        float v[9];
        #pragma unroll
        for (int ky = 0; ky < 3; ky++)
            #pragma unroll
            for (int kx = 0; kx < 3; kx++)
                v[ky * 3 + kx] = sIn[hy + ky][hx + kx];
        #pragma unroll
        for (int c = 0; c < HID; c++) {
            float a = sb1[c];
            #pragma unroll
            for (int k = 0; k < 9; k++) a = fmaf(sW1[c * 9 + k], v[k], a);
            sHid[c][hy][hx] = inside ? fmaxf(a, 0.f) : 0.f;
        }
    }
    __syncthreads();

    // conv2 (16->1) + accumulate into T
    const int ty = threadIdx.y, tx = threadIdx.x;
    float a0 = sb2, a1 = 0.f, a2 = 0.f, a3 = 0.f;
    #pragma unroll
    for (int c = 0; c < HID; c += 4) {
        #pragma unroll
        for (int ky = 0; ky < 3; ky++) {
            #pragma unroll
            for (int kx = 0; kx < 3; kx++) {
                int k = ky * 3 + kx;
                a0 = fmaf(sW2[(c + 0) * 9 + k], sHid[c + 0][ty + ky][tx + kx], a0);
                a1 = fmaf(sW2[(c + 1) * 9 + k], sHid[c + 1][ty + ky][tx + kx], a1);
                a2 = fmaf(sW2[(c + 2) * 9 + k], sHid[c + 2][ty + ky][tx + kx], a2);
                a3 = fmaf(sW2[(c + 3) * 9 + k], sHid[c + 3][ty + ky][tx + kx], a3);
            }
        }
    }
    size_t o = (size_t)n * h * w + (size_t)(y0 + ty) * w + (x0 + tx);
    T[o] += sign * ((a0 + a1) + (a2 + a3));
}

// ---------------------------------------------------------------------------
// K3: transpose + even/odd split:
//   dL[n][r][i] = src[n][i][2r],  dH[n][r][i] = src[n][i][2r+1]
// src: (24,256,512); dL,dH: (24,256,256)
// ---------------------------------------------------------------------------
__global__ void tsplit_kernel(const float* __restrict__ src,
                              float* __restrict__ dL, float* __restrict__ dH) {
    __shared__ float s[32][65];
    int n  = blockIdx.z;
    int r0 = blockIdx.x * 32;
    int b0 = blockIdx.y * 32;
    int tx = threadIdx.x, ty = threadIdx.y;
    const float* S = src + (size_t)n * 256 * 512;
    s[ty][tx]      = S[(size_t)(b0 + ty) * 512 + 2 * r0 + tx];
    s[ty][tx + 32] = S[(size_t)(b0 + ty) * 512 + 2 * r0 + tx + 32];
    __syncthreads();
    size_t o = (size_t)n * 256 * 256 + (size_t)(r0 + ty) * 256 + (b0 + tx);
    dL[o] = s[tx][2 * ty];
    dH[o] = s[tx][2 * ty + 1];
}

// ---------------------------------------------------------------------------
// K4: final transpose-back + batch2channel + concat.
//   out[b, 3*t + c, i, j] = A_t[c*8+b][j][i]
// ---------------------------------------------------------------------------
__global__ void final_kernel(float* __restrict__ out) {
    __shared__ float s[32][33];
    int t = blockIdx.z / NB;
    int n = blockIdx.z % NB;
    const float* g = (t == 0) ? g_A0 : (t == 1) ? g_A1 : (t == 2) ? g_A2 : g_A3;
    int i0 = blockIdx.x * 32, j0 = blockIdx.y * 32;
    int tx = threadIdx.x, ty = threadIdx.y;
    s[ty][tx] = g[(size_t)n * 256 * 256 + (size_t)(j0 + ty) * 256 + (i0 + tx)];
    __syncthreads();
    int c = n >> 3, b = n & 7;
    int ch = t * 3 + c;
    out[(((size_t)b * 12 + ch) * 256 + (i0 + ty)) * 256 + (j0 + tx)] = s[tx][ty];
}

// ---------------------------------------------------------------------------
extern "C" void kernel_launch(void* const* d_in, const int* in_sizes, int n_in,
                              void* d_out, int out_size) {
    const float* x   = (const float*)d_in[0];
    const float* Wp1 = (const float*)d_in[1];
    const float* bp1 = (const float*)d_in[2];
    const float* Wp2 = (const float*)d_in[3];
    const float* bp2 = (const float*)d_in[4];
    const float* Wu1 = (const float*)d_in[5];
    const float* bu1 = (const float*)d_in[6];
    const float* Wu2 = (const float*)d_in[7];
    const float* bu2 = (const float*)d_in[8];
    float* out = (float*)d_out;

    float *pL, *pH, *p0, *p1, *p2, *p3;
    cudaGetSymbolAddress((void**)&pL, g_L);
    cudaGetSymbolAddress((void**)&pH, g_H);
    cudaGetSymbolAddress((void**)&p0, g_A0);
    cudaGetSymbolAddress((void**)&p1, g_A1);
    cudaGetSymbolAddress((void**)&p2, g_A2);
    cudaGetSymbolAddress((void**)&p3, g_A3);

    dim3 blk(TX, TY);

    // stage 0: YUV + row split
    rgb2yuv_split_kernel<<<dim3(2, 512, 8), 256>>>(x);

    // stage 1 lift on (256,512):  H -= subnet(L,p); L += subnet(H,u)
    subnet_kernel<<<dim3(512 / TX, 256 / TY, NB), blk>>>(pL, pH, Wp1, bp1, Wp2, bp2, -1.f, 256, 512);
    subnet_kernel<<<dim3(512 / TX, 256 / TY, NB), blk>>>(pH, pL, Wu1, bu1, Wu2, bu2, +1.f, 256, 512);

    // transpose + split both bands
    tsplit_kernel<<<dim3(8, 8, NB), dim3(32, 32)>>>(pL, p0, p1);  // -> LL, HL
    tsplit_kernel<<<dim3(8, 8, NB), dim3(32, 32)>>>(pH, p2, p3);  // -> LH, HH

    // stage 2 lifts on (256,256)
    dim3 g2(256 / TX, 256 / TY, NB);
    subnet_kernel<<<g2, blk>>>(p0, p1, Wp1, bp1, Wp2, bp2, -1.f, 256, 256);
    subnet_kernel<<<g2, blk>>>(p1, p0, Wu1, bu1, Wu2, bu2, +1.f, 256, 256);
    subnet_kernel<<<g2, blk>>>(p2, p3, Wp1, bp1, Wp2, bp2, -1.f, 256, 256);
    subnet_kernel<<<g2, blk>>>(p3, p2, Wu1, bu1, Wu2, bu2, +1.f, 256, 256);

    // output assembly
    final_kernel<<<dim3(8, 8, 4 * NB), dim3(32, 32)>>>(out);
}

// round 3
// speedup vs baseline: 3.7184x; 3.7184x over previous
#include <cuda_runtime.h>

#define HID 16
#define NB 24

// subnet tile: 32 wide x 32 tall, 256 threads, 4 output rows per thread
#define TW 32
#define TH 32
#define NTHR 256
#define RPT 4
#define HT 34   // hidden tile (TH+2 x TW+2)
#define IT 36   // input tile  (TH+4 x TW+4)

// scratch (device globals: allocation-guard safe)
__device__ float g_L[NB * 256 * 512];
__device__ float g_H[NB * 256 * 512];
__device__ float g_A0[NB * 256 * 256];  // LL
__device__ float g_A1[NB * 256 * 256];  // HL
__device__ float g_A2[NB * 256 * 256];  // LH
__device__ float g_A3[NB * 256 * 256];  // HH

// ---- f32x2 packed helpers (Blackwell) -------------------------------------
__device__ __forceinline__ unsigned long long pack2(float lo, float hi) {
    unsigned long long r;
    asm("mov.b64 %0, {%1, %2};" : "=l"(r) : "f"(lo), "f"(hi));
    return r;
}
__device__ __forceinline__ void unpack2(unsigned long long v, float& lo, float& hi) {
    asm("mov.b64 {%0, %1}, %2;" : "=f"(lo), "=f"(hi) : "l"(v));
}
#define FFMA2(d, a, b) asm("fma.rn.f32x2 %0, %1, %2, %0;" : "+l"(d) : "l"(a), "l"(b))

// ---------------------------------------------------------------------------
// K1: RGB->YUV + even/odd row split.
// x: (8,3,512,512). L/H: (24,256,512) with n = c*8 + b.
// ---------------------------------------------------------------------------
__global__ void rgb2yuv_split_kernel(const float* __restrict__ x) {
    int gx  = blockIdx.x * blockDim.x + threadIdx.x;  // 0..511
    int row = blockIdx.y;                             // 0..511
    int b   = blockIdx.z;                             // 0..7
    const size_t plane = 512 * 512;
    const float* xb = x + (size_t)b * 3 * plane + (size_t)row * 512 + gx;
    float r  = xb[0];
    float g  = xb[plane];
    float bl = xb[2 * plane];
    float Y =  0.299f * r + 0.587f * g + 0.114f * bl;
    float U = -0.147f * r - 0.289f * g + 0.436f * bl;
    float V =  0.615f * r - 0.515f * g - 0.100f * bl;
    float* dst = (row & 1) ? g_H : g_L;
    int i = row >> 1;
    const size_t p2 = 256 * 512;
    size_t off = (size_t)i * 512 + gx;
    dst[(size_t)(0 * 8 + b) * p2 + off] = Y;
    dst[(size_t)(1 * 8 + b) * p2 + off] = U;
    dst[(size_t)(2 * 8 + b) * p2 + off] = V;
}

// ---------------------------------------------------------------------------
// K2: fused subnet:  T += sign * conv2( relu( conv1(I) ) ), SAME padding.
// Hidden channels stored as float2 channel-pairs; math in fma.rn.f32x2.
// Two passes of 4 channel-pairs to bound smem. Hidden values at global
// positions outside the image are ZERO (conv2 SAME-padding semantics).
// ---------------------------------------------------------------------------
__global__ void __launch_bounds__(NTHR) subnet_kernel(
    const float* __restrict__ I, float* __restrict__ T,
    const float* __restrict__ W1, const float* __restrict__ b1,
    const float* __restrict__ W2, const float* __restrict__ b2,
    float sign, int h, int w)
{
    __shared__ float sIn[IT][IT];                       // 5184 B
    __shared__ unsigned long long sHid[4][HT][HT];      // 36992 B
    __shared__ unsigned long long sW1p[8][9];           // packed (c,c+1) weights
    __shared__ unsigned long long sW2p[8][9];
    __shared__ unsigned long long sB1p[8];
    __shared__ float sB2;

    const int tid = threadIdx.x;
    const int n  = blockIdx.z;
    const int x0 = blockIdx.x * TW;
    const int y0 = blockIdx.y * TH;
    const float* In = I + (size_t)n * h * w;

    if (tid < 72) {
        int c2 = tid / 9, k = tid - c2 * 9;
        sW1p[c2][k] = pack2(W1[(2 * c2) * 9 + k], W1[(2 * c2 + 1) * 9 + k]);
        sW2p[c2][k] = pack2(W2[(2 * c2) * 9 + k], W2[(2 * c2 + 1) * 9 + k]);
    }
    if (tid < 8)  sB1p[tid] = pack2(b1[2 * tid], b1[2 * tid + 1]);
    if (tid == 0) sB2 = b2[0];

    // input tile with halo 2 (zero outside image)
    #pragma unroll
    for (int it = 0; it < (IT * IT + NTHR - 1) / NTHR; it++) {
        int idx = tid + it * NTHR;
        if (idx < IT * IT) {
            int iy = idx / IT, ix = idx - iy * IT;
            int gy = y0 + iy - 2, gx = x0 + ix - 2;
            float v = 0.f;
            if (gy >= 0 && gy < h && gx >= 0 && gx < w) v = In[(size_t)gy * w + gx];
            sIn[iy][ix] = v;
        }
    }

    const int lx = tid & 31;           // output column in tile
    const int r0 = (tid >> 5) * RPT;   // first output row in tile

    unsigned long long acc[RPT];
    #pragma unroll
    for (int d = 0; d < RPT; d++) acc[d] = 0ull;

    #pragma unroll
    for (int pass = 0; pass < 2; pass++) {
        __syncthreads();   // pass0: staging done; pass1: conv2 reads done

        // conv1 (+relu) for channel pairs 4*pass .. 4*pass+3
        #pragma unroll
        for (int it = 0; it < (HT * HT + NTHR - 1) / NTHR; it++) {
            int idx = tid + it * NTHR;
            if (idx < HT * HT) {
                int hy = idx / HT, hx = idx - hy * HT;
                int gy = y0 + hy - 1, gx = x0 + hx - 1;
                bool inside = (gy >= 0) && (gy < h) && (gx >= 0) && (gx < w);
                unsigned long long vv[9];
                #pragma unroll
                for (int ky = 0; ky < 3; ky++)
                    #pragma unroll
                    for (int kx = 0; kx < 3; kx++) {
                        float v = sIn[hy + ky][hx + kx];
                        vv[ky * 3 + kx] = pack2(v, v);
                    }
                #pragma unroll
                for (int q = 0; q < 4; q++) {
                    const int cp = pass * 4 + q;
                    unsigned long long a = sB1p[cp];
                    #pragma unroll
                    for (int k = 0; k < 9; k++) FFMA2(a, sW1p[cp][k], vv[k]);
                    float f0, f1;
                    unpack2(a, f0, f1);
                    f0 = inside ? fmaxf(f0, 0.f) : 0.f;
                    f1 = inside ? fmaxf(f1, 0.f) : 0.f;
                    sHid[q][hy][hx] = pack2(f0, f1);
                }
            }
        }
        __syncthreads();

        // conv2 accumulate: rolling rows, each triple reused by up to 3 rows
        #pragma unroll
        for (int q = 0; q < 4; q++) {
            const int cp = pass * 4 + q;
            unsigned long long wq[9];
            #pragma unroll
            for (int k = 0; k < 9; k++) wq[k] = sW2p[cp][k];
            #pragma unroll
            for (int j = 0; j < RPT + 2; j++) {
                unsigned long long T0 = sHid[q][r0 + j][lx];
                unsigned long long T1 = sHid[q][r0 + j][lx + 1];
                unsigned long long T2 = sHid[q][r0 + j][lx + 2];
                #pragma unroll
                for (int d = 0; d < RPT; d++) {
                    const int ky = j - d;
                    if (ky >= 0 && ky <= 2) {
                        FFMA2(acc[d], wq[ky * 3 + 0], T0);
                        FFMA2(acc[d], wq[ky * 3 + 1], T1);
                        FFMA2(acc[d], wq[ky * 3 + 2], T2);
                    }
                }
            }
        }
    }

    const float bias2 = sB2;
    #pragma unroll
    for (int d = 0; d < RPT; d++) {
        float f0, f1;
        unpack2(acc[d], f0, f1);
        float s = (f0 + f1) + bias2;
        size_t o = (size_t)n * h * w + (size_t)(y0 + r0 + d) * w + (x0 + lx);
        T[o] += sign * s;
    }
}

// ---------------------------------------------------------------------------
// K3: transpose + even/odd split:
//   dL[n][r][i] = src[n][i][2r],  dH[n][r][i] = src[n][i][2r+1]
// src: (24,256,512); dL,dH: (24,256,256)
// ---------------------------------------------------------------------------
__global__ void tsplit_kernel(const float* __restrict__ src,
                              float* __restrict__ dL, float* __restrict__ dH) {
    __shared__ float s[32][65];
    int n  = blockIdx.z;
    int r0 = blockIdx.x * 32;
    int b0 = blockIdx.y * 32;
    int tx = threadIdx.x, ty = threadIdx.y;
    const float* S = src + (size_t)n * 256 * 512;
    s[ty][tx]      = S[(size_t)(b0 + ty) * 512 + 2 * r0 + tx];
    s[ty][tx + 32] = S[(size_t)(b0 + ty) * 512 + 2 * r0 + tx + 32];
    __syncthreads();
    size_t o = (size_t)n * 256 * 256 + (size_t)(r0 + ty) * 256 + (b0 + tx);
    dL[o] = s[tx][2 * ty];
    dH[o] = s[tx][2 * ty + 1];
}

// ---------------------------------------------------------------------------
// K4: final transpose-back + batch2channel + concat.
//   out[b, 3*t + c, i, j] = A_t[c*8+b][j][i]
// ---------------------------------------------------------------------------
__global__ void final_kernel(float* __restrict__ out) {
    __shared__ float s[32][33];
    int t = blockIdx.z / NB;
    int n = blockIdx.z % NB;
    const float* g = (t == 0) ? g_A0 : (t == 1) ? g_A1 : (t == 2) ? g_A2 : g_A3;
    int i0 = blockIdx.x * 32, j0 = blockIdx.y * 32;
    int tx = threadIdx.x, ty = threadIdx.y;
    s[ty][tx] = g[(size_t)n * 256 * 256 + (size_t)(j0 + ty) * 256 + (i0 + tx)];
    __syncthreads();
    int c = n >> 3, b = n & 7;
    int ch = t * 3 + c;
    out[(((size_t)b * 12 + ch) * 256 + (i0 + ty)) * 256 + (j0 + tx)] = s[tx][ty];
}

// ---------------------------------------------------------------------------
extern "C" void kernel_launch(void* const* d_in, const int* in_sizes, int n_in,
                              void* d_out, int out_size) {
    const float* x   = (const float*)d_in[0];
    const float* Wp1 = (const float*)d_in[1];
    const float* bp1 = (const float*)d_in[2];
    const float* Wp2 = (const float*)d_in[3];
    const float* bp2 = (const float*)d_in[4];
    const float* Wu1 = (const float*)d_in[5];
    const float* bu1 = (const float*)d_in[6];
    const float* Wu2 = (const float*)d_in[7];
    const float* bu2 = (const float*)d_in[8];
    float* out = (float*)d_out;

    float *pL, *pH, *p0, *p1, *p2, *p3;
    cudaGetSymbolAddress((void**)&pL, g_L);
    cudaGetSymbolAddress((void**)&pH, g_H);
    cudaGetSymbolAddress((void**)&p0, g_A0);
    cudaGetSymbolAddress((void**)&p1, g_A1);
    cudaGetSymbolAddress((void**)&p2, g_A2);
    cudaGetSymbolAddress((void**)&p3, g_A3);

    // stage 0: YUV + row split
    rgb2yuv_split_kernel<<<dim3(2, 512, 8), 256>>>(x);

    // stage 1 lift on (256,512):  H -= subnet(L,p); L += subnet(H,u)
    dim3 g1(512 / TW, 256 / TH, NB);
    subnet_kernel<<<g1, NTHR>>>(pL, pH, Wp1, bp1, Wp2, bp2, -1.f, 256, 512);
    subnet_kernel<<<g1, NTHR>>>(pH, pL, Wu1, bu1, Wu2, bu2, +1.f, 256, 512);

    // transpose + split both bands
    tsplit_kernel<<<dim3(8, 8, NB), dim3(32, 32)>>>(pL, p0, p1);  // -> LL, HL
    tsplit_kernel<<<dim3(8, 8, NB), dim3(32, 32)>>>(pH, p2, p3);  // -> LH, HH

    // stage 2 lifts on (256,256)
    dim3 g2(256 / TW, 256 / TH, NB);
    subnet_kernel<<<g2, NTHR>>>(p0, p1, Wp1, bp1, Wp2, bp2, -1.f, 256, 256);
    subnet_kernel<<<g2, NTHR>>>(p1, p0, Wu1, bu1, Wu2, bu2, +1.f, 256, 256);
    subnet_kernel<<<g2, NTHR>>>(p2, p3, Wp1, bp1, Wp2, bp2, -1.f, 256, 256);
    subnet_kernel<<<g2, NTHR>>>(p3, p2, Wu1, bu1, Wu2, bu2, +1.f, 256, 256);

    // output assembly
    final_kernel<<<dim3(8, 8, 4 * NB), dim3(32, 32)>>>(out);
}

// round 4
// speedup vs baseline: 3.7648x; 1.0125x over previous
#include <cuda_runtime.h>

#define HID 16
#define NB 24

// subnet tile: 32 wide x 32 tall, 256 threads, 4 output rows per thread
#define TW 32
#define TH 32
#define NTHR 256
#define RPT 4
#define HT 34   // hidden tile (TH+2 x TW+2)
#define IT 36   // input tile  (TH+4 x TW+4)

typedef unsigned long long ull;

// scratch (device globals: allocation-guard safe)
__device__ float g_L[NB * 256 * 512];
__device__ float g_H[NB * 256 * 512];
__device__ float g_A0[NB * 256 * 256];  // LL
__device__ float g_A1[NB * 256 * 256];  // HL
__device__ float g_A2[NB * 256 * 256];  // LH
__device__ float g_A3[NB * 256 * 256];  // HH

// ---- f32x2 packed helpers (Blackwell) -------------------------------------
__device__ __forceinline__ ull pack2(float lo, float hi) {
    ull r;
    asm("mov.b64 %0, {%1, %2};" : "=l"(r) : "f"(lo), "f"(hi));
    return r;
}
__device__ __forceinline__ void unpack2(ull v, float& lo, float& hi) {
    asm("mov.b64 {%0, %1}, %2;" : "=f"(lo), "=f"(hi) : "l"(v));
}
#define FFMA2(d, a, b) asm("fma.rn.f32x2 %0, %1, %2, %0;" : "+l"(d) : "l"(a), "l"(b))

// ---------------------------------------------------------------------------
// K1: RGB->YUV + even/odd row split.
// ---------------------------------------------------------------------------
__global__ void rgb2yuv_split_kernel(const float* __restrict__ x) {
    int gx  = blockIdx.x * blockDim.x + threadIdx.x;  // 0..511
    int row = blockIdx.y;                             // 0..511
    int b   = blockIdx.z;                             // 0..7
    const size_t plane = 512 * 512;
    const float* xb = x + (size_t)b * 3 * plane + (size_t)row * 512 + gx;
    float r  = xb[0];
    float g  = xb[plane];
    float bl = xb[2 * plane];
    float Y =  0.299f * r + 0.587f * g + 0.114f * bl;
    float U = -0.147f * r - 0.289f * g + 0.436f * bl;
    float V =  0.615f * r - 0.515f * g - 0.100f * bl;
    float* dst = (row & 1) ? g_H : g_L;
    int i = row >> 1;
    const size_t p2 = 256 * 512;
    size_t off = (size_t)i * 512 + gx;
    dst[(size_t)(0 * 8 + b) * p2 + off] = Y;
    dst[(size_t)(1 * 8 + b) * p2 + off] = U;
    dst[(size_t)(2 * 8 + b) * p2 + off] = V;
}

// ---------------------------------------------------------------------------
// K2: fused subnet:  T += sign * conv2( relu( conv1(I) ) ), SAME padding.
// Hidden channels stored as f32x2 channel-pairs; math in fma.rn.f32x2.
// Two passes of 4 channel-pairs; conv1 runs over 2-pixel strips with
// vectorized input loads and register-resident weights; hidden stored
// via 128-bit stores. Hidden values outside the image are ZERO.
// Two independent (I,T) streams selectable by blockIdx.z (merged launches).
// ---------------------------------------------------------------------------
__global__ void __launch_bounds__(NTHR) subnet_kernel(
    const float* __restrict__ I0, float* __restrict__ T0,
    const float* __restrict__ I1, float* __restrict__ T1,
    const float* __restrict__ W1, const float* __restrict__ b1,
    const float* __restrict__ W2, const float* __restrict__ b2,
    float sign, int h, int w)
{
    __shared__ __align__(16) float sIn[IT][IT];
    __shared__ __align__(16) ull sHid[4][HT][HT];
    __shared__ ull sW1p[8][9];
    __shared__ ull sW2p[8][9];
    __shared__ ull sB1p[8];
    __shared__ float sB2;

    const int tid = threadIdx.x;
    int n = blockIdx.z;
    const float* I = I0;
    float* T = T0;
    if (n >= NB) { n -= NB; I = I1; T = T1; }
    const int x0 = blockIdx.x * TW;
    const int y0 = blockIdx.y * TH;
    const float* In = I + (size_t)n * h * w;

    if (tid < 72) {
        int c2 = tid / 9, k = tid - c2 * 9;
        sW1p[c2][k] = pack2(W1[(2 * c2) * 9 + k], W1[(2 * c2 + 1) * 9 + k]);
        sW2p[c2][k] = pack2(W2[(2 * c2) * 9 + k], W2[(2 * c2 + 1) * 9 + k]);
    }
    if (tid < 8)  sB1p[tid] = pack2(b1[2 * tid], b1[2 * tid + 1]);
    if (tid == 0) sB2 = b2[0];

    // input tile with halo 2 (zero outside image)
    #pragma unroll
    for (int it = 0; it < (IT * IT + NTHR - 1) / NTHR; it++) {
        int idx = tid + it * NTHR;
        if (idx < IT * IT) {
            int iy = idx / IT, ix = idx - iy * IT;
            int gy = y0 + iy - 2, gx = x0 + ix - 2;
            float v = 0.f;
            if (gy >= 0 && gy < h && gx >= 0 && gx < w) v = In[(size_t)gy * w + gx];
            sIn[iy][ix] = v;
        }
    }

    const int lx = tid & 31;           // output column in tile
    const int r0 = (tid >> 5) * RPT;   // first output row in tile

    ull acc[RPT];
    #pragma unroll
    for (int d = 0; d < RPT; d++) acc[d] = 0ull;

    #pragma unroll
    for (int pass = 0; pass < 2; pass++) {
        __syncthreads();   // pass0: staging done; pass1: conv2 reads done

        // hoist this pass's conv1 weights into registers (broadcast loads)
        ull w1r[4][9];
        #pragma unroll
        for (int q = 0; q < 4; q++)
            #pragma unroll
            for (int k = 0; k < 9; k++) w1r[q][k] = sW1p[pass * 4 + q][k];
        ull bb[4];
        #pragma unroll
        for (int q = 0; q < 4; q++) bb[q] = sB1p[pass * 4 + q];

        // conv1 (+relu) over 2-pixel strips: 17 strips x 34 rows
        for (int idx = tid; idx < HT * (HT / 2); idx += NTHR) {
            int hy = idx / (HT / 2);
            int hp = idx - hy * (HT / 2);
            int hx = 2 * hp;
            int gy = y0 + hy - 1, gx = x0 + hx - 1;
            bool rowin = (gy >= 0) && (gy < h);
            bool inA = rowin && (gx >= 0) && (gx < w);
            bool inB = rowin && (gx + 1 < w);

            // taps: cols hx..hx+3 of sIn rows hy..hy+2 (2 aligned float2/row)
            ull sp[3][4];
            #pragma unroll
            for (int ky = 0; ky < 3; ky++) {
                float2 abv = *(const float2*)&sIn[hy + ky][hx];
                float2 cdv = *(const float2*)&sIn[hy + ky][hx + 2];
                sp[ky][0] = pack2(abv.x, abv.x);
                sp[ky][1] = pack2(abv.y, abv.y);
                sp[ky][2] = pack2(cdv.x, cdv.x);
                sp[ky][3] = pack2(cdv.y, cdv.y);
            }
            #pragma unroll
            for (int q = 0; q < 4; q++) {
                ull aA = bb[q], aB = bb[q];
                #pragma unroll
                for (int ky = 0; ky < 3; ky++)
                    #pragma unroll
                    for (int kx = 0; kx < 3; kx++) {
                        ull wv = w1r[q][ky * 3 + kx];
                        FFMA2(aA, wv, sp[ky][kx]);
                        FFMA2(aB, wv, sp[ky][kx + 1]);
                    }
                float a0v, a1v, b0v, b1v;
                unpack2(aA, a0v, a1v);
                unpack2(aB, b0v, b1v);
                ulonglong2 st;
                st.x = pack2(inA ? fmaxf(a0v, 0.f) : 0.f, inA ? fmaxf(a1v, 0.f) : 0.f);
                st.y = pack2(inB ? fmaxf(b0v, 0.f) : 0.f, inB ? fmaxf(b1v, 0.f) : 0.f);
                *(ulonglong2*)&sHid[q][hy][hx] = st;
            }
        }
        __syncthreads();

        // conv2 accumulate: rolling rows, each triple reused by up to 3 rows
        #pragma unroll
        for (int q = 0; q < 4; q++) {
            const int cp = pass * 4 + q;
            ull wq[9];
            #pragma unroll
            for (int k = 0; k < 9; k++) wq[k] = sW2p[cp][k];
            #pragma unroll
            for (int j = 0; j < RPT + 2; j++) {
                ull T0v = sHid[q][r0 + j][lx];
                ull T1v = sHid[q][r0 + j][lx + 1];
                ull T2v = sHid[q][r0 + j][lx + 2];
                #pragma unroll
                for (int d = 0; d < RPT; d++) {
                    const int ky = j - d;
                    if (ky >= 0 && ky <= 2) {
                        FFMA2(acc[d], wq[ky * 3 + 0], T0v);
                        FFMA2(acc[d], wq[ky * 3 + 1], T1v);
                        FFMA2(acc[d], wq[ky * 3 + 2], T2v);
                    }
                }
            }
        }
    }

    const float bias2 = sB2;
    #pragma unroll
    for (int d = 0; d < RPT; d++) {
        float f0, f1;
        unpack2(acc[d], f0, f1);
        float s = (f0 + f1) + bias2;
        size_t o = (size_t)n * h * w + (size_t)(y0 + r0 + d) * w + (x0 + lx);
        T[o] += sign * s;
    }
}

// ---------------------------------------------------------------------------
// K3: transpose + even/odd split (both bands in one launch):
//   z<NB:  g_L -> (g_A0, g_A1);  z>=NB:  g_H -> (g_A2, g_A3)
// ---------------------------------------------------------------------------
__global__ void tsplit_kernel() {
    __shared__ float s[32][65];
    int z = blockIdx.z;
    const float* src = (z < NB) ? g_L : g_H;
    float* dL = (z < NB) ? g_A0 : g_A2;
    float* dH = (z < NB) ? g_A1 : g_A3;
    int n  = (z < NB) ? z : z - NB;
    int r0 = blockIdx.x * 32;
    int b0 = blockIdx.y * 32;
    int tx = threadIdx.x, ty = threadIdx.y;
    const float* S = src + (size_t)n * 256 * 512;
    s[ty][tx]      = S[(size_t)(b0 + ty) * 512 + 2 * r0 + tx];
    s[ty][tx + 32] = S[(size_t)(b0 + ty) * 512 + 2 * r0 + tx + 32];
    __syncthreads();
    size_t o = (size_t)n * 256 * 256 + (size_t)(r0 + ty) * 256 + (b0 + tx);
    dL[o] = s[tx][2 * ty];
    dH[o] = s[tx][2 * ty + 1];
}

// ---------------------------------------------------------------------------
// K4: final transpose-back + batch2channel + concat.
//   out[b, 3*t + c, i, j] = A_t[c*8+b][j][i]
// ---------------------------------------------------------------------------
__global__ void final_kernel(float* __restrict__ out) {
    __shared__ float s[32][33];
    int t = blockIdx.z / NB;
    int n = blockIdx.z % NB;
    const float* g = (t == 0) ? g_A0 : (t == 1) ? g_A1 : (t == 2) ? g_A2 : g_A3;
    int i0 = blockIdx.x * 32, j0 = blockIdx.y * 32;
    int tx = threadIdx.x, ty = threadIdx.y;
    s[ty][tx] = g[(size_t)n * 256 * 256 + (size_t)(j0 + ty) * 256 + (i0 + tx)];
    __syncthreads();
    int c = n >> 3, b = n & 7;
    int ch = t * 3 + c;
    out[(((size_t)b * 12 + ch) * 256 + (i0 + ty)) * 256 + (j0 + tx)] = s[tx][ty];
}

// ---------------------------------------------------------------------------
extern "C" void kernel_launch(void* const* d_in, const int* in_sizes, int n_in,
                              void* d_out, int out_size) {
    const float* x   = (const float*)d_in[0];
    const float* Wp1 = (const float*)d_in[1];
    const float* bp1 = (const float*)d_in[2];
    const float* Wp2 = (const float*)d_in[3];
    const float* bp2 = (const float*)d_in[4];
    const float* Wu1 = (const float*)d_in[5];
    const float* bu1 = (const float*)d_in[6];
    const float* Wu2 = (const float*)d_in[7];
    const float* bu2 = (const float*)d_in[8];
    float* out = (float*)d_out;

    float *pL, *pH, *p0, *p1, *p2, *p3;
    cudaGetSymbolAddress((void**)&pL, g_L);
    cudaGetSymbolAddress((void**)&pH, g_H);
    cudaGetSymbolAddress((void**)&p0, g_A0);
    cudaGetSymbolAddress((void**)&p1, g_A1);
    cudaGetSymbolAddress((void**)&p2, g_A2);
    cudaGetSymbolAddress((void**)&p3, g_A3);

    // 0: YUV + row split
    rgb2yuv_split_kernel<<<dim3(2, 512, 8), 256>>>(x);

    // 1-2: stage 1 lift on (256,512)
    dim3 g1(512 / TW, 256 / TH, NB);
    subnet_kernel<<<g1, NTHR>>>(pL, pH, pL, pH, Wp1, bp1, Wp2, bp2, -1.f, 256, 512);
    subnet_kernel<<<g1, NTHR>>>(pH, pL, pH, pL, Wu1, bu1, Wu2, bu2, +1.f, 256, 512);

    // 3: transpose + split both bands (merged)
    tsplit_kernel<<<dim3(8, 8, 2 * NB), dim3(32, 32)>>>();

    // 4-5: stage 2 lifts on (256,256) — both independent chains per launch
    dim3 g2(256 / TW, 256 / TH, 2 * NB);
    subnet_kernel<<<g2, NTHR>>>(p0, p1, p2, p3, Wp1, bp1, Wp2, bp2, -1.f, 256, 256);
    subnet_kernel<<<g2, NTHR>>>(p1, p0, p3, p2, Wu1, bu1, Wu2, bu2, +1.f, 256, 256);

    // 6: output assembly
    final_kernel<<<dim3(8, 8, 4 * NB), dim3(32, 32)>>>(out);
}

// round 5
// speedup vs baseline: 3.7692x; 1.0012x over previous
#include <cuda_runtime.h>

#define HID 16
#define NB 24

// subnet tile: 32 wide x 32 tall, 256 threads, 4 output rows per thread
#define TW 32
#define TH 32
#define NTHR 256
#define RPT 4
#define HT 34   // hidden tile (TH+2 x TW+2)
#define IT 36   // input tile  (TH+4 x TW+4)

typedef unsigned long long ull;

// scratch (device globals: allocation-guard safe)
__device__ float g_L[NB * 256 * 512];
__device__ float g_H[NB * 256 * 512];
__device__ float g_A0[NB * 256 * 256];  // LL
__device__ float g_A1[NB * 256 * 256];  // HL
__device__ float g_A2[NB * 256 * 256];  // LH
__device__ float g_A3[NB * 256 * 256];  // HH

// ---- f32x2 packed helpers (Blackwell) -------------------------------------
__device__ __forceinline__ ull pack2(float lo, float hi) {
    ull r;
    asm("mov.b64 %0, {%1, %2};" : "=l"(r) : "f"(lo), "f"(hi));
    return r;
}
__device__ __forceinline__ void unpack2(ull v, float& lo, float& hi) {
    asm("mov.b64 {%0, %1}, %2;" : "=f"(lo), "=f"(hi) : "l"(v));
}
#define FFMA2(d, a, b) asm("fma.rn.f32x2 %0, %1, %2, %0;" : "+l"(d) : "l"(a), "l"(b))

// ---------------------------------------------------------------------------
// K1: RGB->YUV + even/odd row split.
// ---------------------------------------------------------------------------
__global__ void rgb2yuv_split_kernel(const float* __restrict__ x) {
    int gx  = blockIdx.x * blockDim.x + threadIdx.x;  // 0..511
    int row = blockIdx.y;                             // 0..511
    int b   = blockIdx.z;                             // 0..7
    const size_t plane = 512 * 512;
    const float* xb = x + (size_t)b * 3 * plane + (size_t)row * 512 + gx;
    float r  = xb[0];
    float g  = xb[plane];
    float bl = xb[2 * plane];
    float Y =  0.299f * r + 0.587f * g + 0.114f * bl;
    float U = -0.147f * r - 0.289f * g + 0.436f * bl;
    float V =  0.615f * r - 0.515f * g - 0.100f * bl;
    float* dst = (row & 1) ? g_H : g_L;
    int i = row >> 1;
    const size_t p2 = 256 * 512;
    size_t off = (size_t)i * 512 + gx;
    dst[(size_t)(0 * 8 + b) * p2 + off] = Y;
    dst[(size_t)(1 * 8 + b) * p2 + off] = U;
    dst[(size_t)(2 * 8 + b) * p2 + off] = V;
}

// ---------------------------------------------------------------------------
// K2: fused subnet:  T += sign * conv2( relu( conv1(I) ) ), SAME padding.
// Hidden channels stored as f32x2 channel-pairs; math in fma.rn.f32x2.
// Two passes of 4 channel-pairs; conv1 runs over 2-pixel strips with
// vectorized input loads and register-resident weights; hidden stored
// via 128-bit stores. Hidden values outside the image are ZERO.
// Two independent (I,T) streams selectable by blockIdx.z (merged launches).
// ---------------------------------------------------------------------------
__global__ void __launch_bounds__(NTHR) subnet_kernel(
    const float* __restrict__ I0, float* __restrict__ T0,
    const float* __restrict__ I1, float* __restrict__ T1,
    const float* __restrict__ W1, const float* __restrict__ b1,
    const float* __restrict__ W2, const float* __restrict__ b2,
    float sign, int h, int w)
{
    __shared__ __align__(16) float sIn[IT][IT];
    __shared__ __align__(16) ull sHid[4][HT][HT];
    __shared__ ull sW1p[8][9];
    __shared__ ull sW2p[8][9];
    __shared__ ull sB1p[8];
    __shared__ float sB2;

    const int tid = threadIdx.x;
    int n = blockIdx.z;
    const float* I = I0;
    float* T = T0;
    if (n >= NB) { n -= NB; I = I1; T = T1; }
    const int x0 = blockIdx.x * TW;
    const int y0 = blockIdx.y * TH;
    const float* In = I + (size_t)n * h * w;

    if (tid < 72) {
        int c2 = tid / 9, k = tid - c2 * 9;
        sW1p[c2][k] = pack2(W1[(2 * c2) * 9 + k], W1[(2 * c2 + 1) * 9 + k]);
        sW2p[c2][k] = pack2(W2[(2 * c2) * 9 + k], W2[(2 * c2 + 1) * 9 + k]);
    }
    if (tid < 8)  sB1p[tid] = pack2(b1[2 * tid], b1[2 * tid + 1]);
    if (tid == 0) sB2 = b2[0];

    // input tile with halo 2 (zero outside image)
    #pragma unroll
    for (int it = 0; it < (IT * IT + NTHR - 1) / NTHR; it++) {
        int idx = tid + it * NTHR;
        if (idx < IT * IT) {
            int iy = idx / IT, ix = idx - iy * IT;
            int gy = y0 + iy - 2, gx = x0 + ix - 2;
            float v = 0.f;
            if (gy >= 0 && gy < h && gx >= 0 && gx < w) v = In[(size_t)gy * w + gx];
            sIn[iy][ix] = v;
        }
    }

    const int lx = tid & 31;           // output column in tile
    const int r0 = (tid >> 5) * RPT;   // first output row in tile

    ull acc[RPT];
    #pragma unroll
    for (int d = 0; d < RPT; d++) acc[d] = 0ull;

    #pragma unroll
    for (int pass = 0; pass < 2; pass++) {
        __syncthreads();   // pass0: staging done; pass1: conv2 reads done

        // hoist this pass's conv1 weights into registers (broadcast loads)
        ull w1r[4][9];
        #pragma unroll
        for (int q = 0; q < 4; q++)
            #pragma unroll
            for (int k = 0; k < 9; k++) w1r[q][k] = sW1p[pass * 4 + q][k];
        ull bb[4];
        #pragma unroll
        for (int q = 0; q < 4; q++) bb[q] = sB1p[pass * 4 + q];

        // conv1 (+relu) over 2-pixel strips: 17 strips x 34 rows
        for (int idx = tid; idx < HT * (HT / 2); idx += NTHR) {
            int hy = idx / (HT / 2);
            int hp = idx - hy * (HT / 2);
            int hx = 2 * hp;
            int gy = y0 + hy - 1, gx = x0 + hx - 1;
            bool rowin = (gy >= 0) && (gy < h);
            bool inA = rowin && (gx >= 0) && (gx < w);
            bool inB = rowin && (gx + 1 < w);

            // taps: cols hx..hx+3 of sIn rows hy..hy+2 (2 aligned float2/row)
            ull sp[3][4];
            #pragma unroll
            for (int ky = 0; ky < 3; ky++) {
                float2 abv = *(const float2*)&sIn[hy + ky][hx];
                float2 cdv = *(const float2*)&sIn[hy + ky][hx + 2];
                sp[ky][0] = pack2(abv.x, abv.x);
                sp[ky][1] = pack2(abv.y, abv.y);
                sp[ky][2] = pack2(cdv.x, cdv.x);
                sp[ky][3] = pack2(cdv.y, cdv.y);
            }
            #pragma unroll
            for (int q = 0; q < 4; q++) {
                ull aA = bb[q], aB = bb[q];
                #pragma unroll
                for (int ky = 0; ky < 3; ky++)
                    #pragma unroll
                    for (int kx = 0; kx < 3; kx++) {
                        ull wv = w1r[q][ky * 3 + kx];
                        FFMA2(aA, wv, sp[ky][kx]);
                        FFMA2(aB, wv, sp[ky][kx + 1]);
                    }
                float a0v, a1v, b0v, b1v;
                unpack2(aA, a0v, a1v);
                unpack2(aB, b0v, b1v);
                ulonglong2 st;
                st.x = pack2(inA ? fmaxf(a0v, 0.f) : 0.f, inA ? fmaxf(a1v, 0.f) : 0.f);
                st.y = pack2(inB ? fmaxf(b0v, 0.f) : 0.f, inB ? fmaxf(b1v, 0.f) : 0.f);
                *(ulonglong2*)&sHid[q][hy][hx] = st;
            }
        }
        __syncthreads();

        // conv2 accumulate: rolling rows, each triple reused by up to 3 rows
        #pragma unroll
        for (int q = 0; q < 4; q++) {
            const int cp = pass * 4 + q;
            ull wq[9];
            #pragma unroll
            for (int k = 0; k < 9; k++) wq[k] = sW2p[cp][k];
            #pragma unroll
            for (int j = 0; j < RPT + 2; j++) {
                ull T0v = sHid[q][r0 + j][lx];
                ull T1v = sHid[q][r0 + j][lx + 1];
                ull T2v = sHid[q][r0 + j][lx + 2];
                #pragma unroll
                for (int d = 0; d < RPT; d++) {
                    const int ky = j - d;
                    if (ky >= 0 && ky <= 2) {
                        FFMA2(acc[d], wq[ky * 3 + 0], T0v);
                        FFMA2(acc[d], wq[ky * 3 + 1], T1v);
                        FFMA2(acc[d], wq[ky * 3 + 2], T2v);
                    }
                }
            }
        }
    }

    const float bias2 = sB2;
    #pragma unroll
    for (int d = 0; d < RPT; d++) {
        float f0, f1;
        unpack2(acc[d], f0, f1);
        float s = (f0 + f1) + bias2;
        size_t o = (size_t)n * h * w + (size_t)(y0 + r0 + d) * w + (x0 + lx);
        T[o] += sign * s;
    }
}

// ---------------------------------------------------------------------------
// K3: transpose + even/odd split (both bands in one launch):
//   z<NB:  g_L -> (g_A0, g_A1);  z>=NB:  g_H -> (g_A2, g_A3)
// ---------------------------------------------------------------------------
__global__ void tsplit_kernel() {
    __shared__ float s[32][65];
    int z = blockIdx.z;
    const float* src = (z < NB) ? g_L : g_H;
    float* dL = (z < NB) ? g_A0 : g_A2;
    float* dH = (z < NB) ? g_A1 : g_A3;
    int n  = (z < NB) ? z : z - NB;
    int r0 = blockIdx.x * 32;
    int b0 = blockIdx.y * 32;
    int tx = threadIdx.x, ty = threadIdx.y;
    const float* S = src + (size_t)n * 256 * 512;
    s[ty][tx]      = S[(size_t)(b0 + ty) * 512 + 2 * r0 + tx];
    s[ty][tx + 32] = S[(size_t)(b0 + ty) * 512 + 2 * r0 + tx + 32];
    __syncthreads();
    size_t o = (size_t)n * 256 * 256 + (size_t)(r0 + ty) * 256 + (b0 + tx);
    dL[o] = s[tx][2 * ty];
    dH[o] = s[tx][2 * ty + 1];
}

// ---------------------------------------------------------------------------
// K4: final transpose-back + batch2channel + concat.
//   out[b, 3*t + c, i, j] = A_t[c*8+b][j][i]
// ---------------------------------------------------------------------------
__global__ void final_kernel(float* __restrict__ out) {
    __shared__ float s[32][33];
    int t = blockIdx.z / NB;
    int n = blockIdx.z % NB;
    const float* g = (t == 0) ? g_A0 : (t == 1) ? g_A1 : (t == 2) ? g_A2 : g_A3;
    int i0 = blockIdx.x * 32, j0 = blockIdx.y * 32;
    int tx = threadIdx.x, ty = threadIdx.y;
    s[ty][tx] = g[(size_t)n * 256 * 256 + (size_t)(j0 + ty) * 256 + (i0 + tx)];
    __syncthreads();
    int c = n >> 3, b = n & 7;
    int ch = t * 3 + c;
    out[(((size_t)b * 12 + ch) * 256 + (i0 + ty)) * 256 + (j0 + tx)] = s[tx][ty];
}

// ---------------------------------------------------------------------------
extern "C" void kernel_launch(void* const* d_in, const int* in_sizes, int n_in,
                              void* d_out, int out_size) {
    const float* x   = (const float*)d_in[0];
    const float* Wp1 = (const float*)d_in[1];
    const float* bp1 = (const float*)d_in[2];
    const float* Wp2 = (const float*)d_in[3];
    const float* bp2 = (const float*)d_in[4];
    const float* Wu1 = (const float*)d_in[5];
    const float* bu1 = (const float*)d_in[6];
    const float* Wu2 = (const float*)d_in[7];
    const float* bu2 = (const float*)d_in[8];
    float* out = (float*)d_out;

    float *pL, *pH, *p0, *p1, *p2, *p3;
    cudaGetSymbolAddress((void**)&pL, g_L);
    cudaGetSymbolAddress((void**)&pH, g_H);
    cudaGetSymbolAddress((void**)&p0, g_A0);
    cudaGetSymbolAddress((void**)&p1, g_A1);
    cudaGetSymbolAddress((void**)&p2, g_A2);
    cudaGetSymbolAddress((void**)&p3, g_A3);

    // 0: YUV + row split
    rgb2yuv_split_kernel<<<dim3(2, 512, 8), 256>>>(x);

    // 1-2: stage 1 lift on (256,512)
    dim3 g1(512 / TW, 256 / TH, NB);
    subnet_kernel<<<g1, NTHR>>>(pL, pH, pL, pH, Wp1, bp1, Wp2, bp2, -1.f, 256, 512);
    subnet_kernel<<<g1, NTHR>>>(pH, pL, pH, pL, Wu1, bu1, Wu2, bu2, +1.f, 256, 512);

    // 3: transpose + split both bands (merged)
    tsplit_kernel<<<dim3(8, 8, 2 * NB), dim3(32, 32)>>>();

    // 4-5: stage 2 lifts on (256,256) — both independent chains per launch
    dim3 g2(256 / TW, 256 / TH, 2 * NB);
    subnet_kernel<<<g2, NTHR>>>(p0, p1, p2, p3, Wp1, bp1, Wp2, bp2, -1.f, 256, 256);
    subnet_kernel<<<g2, NTHR>>>(p1, p0, p3, p2, Wu1, bu1, Wu2, bu2, +1.f, 256, 256);

    // 6: output assembly
    final_kernel<<<dim3(8, 8, 4 * NB), dim3(32, 32)>>>(out);
}